// round 17
// baseline (speedup 1.0000x reference)
#include <cuda_runtime.h>
#include <cuda_fp16.h>
#include <cstdint>
#include <math.h>

// ============================================================================
// Globals
// ============================================================================

__device__ double g_sum[2];
__device__ unsigned int g_done = 0;   // wraps back to 0 each launch

// fp16 panels (pre-scaled by sqrt(log2e)), [tb = t*4+b][pos][c] layout:
#define L0_OFF 0
#define L1_OFF 2097152
__device__ __half g_scratch[3145728];

#define SQRT_LOG2E 1.2011224087f

// ============================================================================
// Pre-convert: fp32 [b][c][pos] -> fp16 panel [tb][pos][C] * sqrt(log2e).
// Vectorized: float4 global loads, transposed smem ([p][c], stride C+1),
// uint2 (4x half) global stores.
// ============================================================================
template <int C>
__device__ __forceinline__ void convert_body(
    const float* __restrict__ f1, const float* __restrict__ f2,
    int HW, int off, int bx, float* tile)
{
    constexpr int STC = C + 1;
    const int t = blockIdx.z, b = blockIdx.y;
    const int pos0 = bx * 64;
    const float* src = (t ? f2 : f1) + (size_t)b * C * HW;

    // load: C*64 floats as float4 (4 consecutive pos), store transposed
    #pragma unroll
    for (int q = 0; q < (C * 16) / 256; ++q) {
        const int v = q * 256 + threadIdx.x;
        const int c = v >> 4, pq = v & 15;          // pq: group of 4 pos
        const float4 d = *(const float4*)(src + (size_t)c * HW + pos0 + pq * 4);
        tile[(pq * 4 + 0) * STC + c] = d.x;
        tile[(pq * 4 + 1) * STC + c] = d.y;
        tile[(pq * 4 + 2) * STC + c] = d.z;
        tile[(pq * 4 + 3) * STC + c] = d.w;
    }
    __syncthreads();

    __half* o = g_scratch + off + ((size_t)(t * 4 + b) * HW + pos0) * C;
    constexpr int CQ = C / 4;
    #pragma unroll
    for (int q = 0; q < (64 * CQ) / 256; ++q) {
        const int v = q * 256 + threadIdx.x;
        const int p = v / CQ, c0 = (v % CQ) * 4;
        const float* tp = tile + p * STC + c0;
        __half2 lo = __floats2half2_rn(tp[0] * SQRT_LOG2E, tp[1] * SQRT_LOG2E);
        __half2 hi = __floats2half2_rn(tp[2] * SQRT_LOG2E, tp[3] * SQRT_LOG2E);
        uint2 pk;
        pk.x = *reinterpret_cast<uint32_t*>(&lo);
        pk.y = *reinterpret_cast<uint32_t*>(&hi);
        *reinterpret_cast<uint2*>(o + (size_t)p * C + c0) = pk;
    }
}

__global__ void __launch_bounds__(256)
convert_fused(const float* __restrict__ f1_0, const float* __restrict__ f2_0,
              const float* __restrict__ f1_1, const float* __restrict__ f2_1)
{
    if (blockIdx.x == 0 && blockIdx.y == 0 && blockIdx.z == 0 &&
        threadIdx.x == 0) {
        g_sum[0] = 0.0; g_sum[1] = 0.0;
    }
    __shared__ float tile[64 * 129];
    if (blockIdx.x < 64)
        convert_body<64>(f1_0, f2_0, 4096, L0_OFF, blockIdx.x, tile);
    else
        convert_body<128>(f1_1, f2_1, 1024, L1_OFF, blockIdx.x - 64, tile);
}

// ============================================================================
// PTX helpers (sm_80+ vocabulary only)
// ============================================================================

__device__ __forceinline__ uint32_t smem_to_u32(const void* p) {
    uint32_t a;
    asm("{ .reg .u64 t; cvta.to.shared.u64 t, %1; cvt.u32.u64 %0, t; }"
        : "=r"(a) : "l"(p));
    return a;
}

__device__ __forceinline__ void ldmatrix_x4(uint32_t* r, uint32_t addr) {
    asm volatile(
        "ldmatrix.sync.aligned.m8n8.x4.shared.b16 {%0,%1,%2,%3}, [%4];"
        : "=r"(r[0]), "=r"(r[1]), "=r"(r[2]), "=r"(r[3]) : "r"(addr));
}

// fp16-accumulate MMA: D (2 regs of half2) += A @ B^T
__device__ __forceinline__ void mma_16816_h(uint32_t* d, const uint32_t* a,
                                            const uint32_t* b) {
    asm volatile(
        "mma.sync.aligned.m16n8k16.row.col.f16.f16.f16.f16 "
        "{%0,%1}, {%2,%3,%4,%5}, {%6,%7}, {%0,%1};"
        : "+r"(d[0]), "+r"(d[1])
        : "r"(a[0]), "r"(a[1]), "r"(a[2]), "r"(a[3]), "r"(b[0]), "r"(b[1]));
}

__device__ __forceinline__ void cp_async16(uint32_t saddr, const void* gaddr) {
    asm volatile("cp.async.cg.shared.global [%0], [%1], 16;"
                 :: "r"(saddr), "l"(gaddr));
}
#define CP_COMMIT() asm volatile("cp.async.commit_group;" ::: "memory")
#define CP_WAIT(n)  asm volatile("cp.async.wait_group %0;" :: "n"(n) : "memory")

__device__ __forceinline__ __half2 u2h(uint32_t v) {
    return *reinterpret_cast<__half2*>(&v);
}
__device__ __forceinline__ uint32_t h2u(__half2 v) {
    return *reinterpret_cast<uint32_t*>(&v);
}

// single-instruction f16x2 2^x
__device__ __forceinline__ __half2 ex2_h2(__half2 x) {
    uint32_t r, xi = h2u(x);
    asm("ex2.approx.f16x2 %0, %1;" : "=r"(r) : "r"(xi));
    return u2h(r);
}

// fast per-element reciprocal of a half2 via 2x rcp.approx.f32
__device__ __forceinline__ __half2 rcp_h2(__half2 s) {
    float lo = __low2float(s), hi = __high2float(s);
    float rlo, rhi;
    asm("rcp.approx.f32 %0, %1;" : "=f"(rlo) : "f"(lo));
    asm("rcp.approx.f32 %0, %1;" : "=f"(rhi) : "f"(hi));
    return __floats2half2_rn(rlo, rhi);
}

// ============================================================================
// Fused Gram body (mma.sync fp16 acc) + two-phase f16x2 softmax + |diff|.
// 64x64 tile, triangular index k; 8 warps (4x2), warp 16m x 32n.
// ============================================================================
template <int C, int NSTAGES>
__device__ __forceinline__ void gram_body(int k, int HW, int off, int level,
                                          char* smem)
{
    // ---- triangular decode: k -> (ti, tj), tj >= ti ----
    int a = (int)((sqrtf(8.0f * k + 1.0f) - 1.0f) * 0.5f);
    while ((a + 1) * (a + 2) / 2 <= k) ++a;
    while (a * (a + 1) / 2 > k) --a;
    const int ti = k - a * (a + 1) / 2;   // 0..a
    const int tj = a;                     // tj >= ti

    constexpr int NCH = C / 8;                 // 16B chunks per row
    constexpr int TILE_B = (C / 64) * 8192;    // 64 rows x 2C bytes
    constexpr int STAGE_B = 2 * TILE_B;        // A | B
    constexpr int KSTEPS = C / 16;
    constexpr int NLOAD = (64 * NCH) / 256;    // cp.async iters per tile/thread

    const uint32_t sb = smem_to_u32(smem);
    uint32_t* aff = (uint32_t*)(smem + NSTAGES * STAGE_B);  // [b*8+r][tid] 32 KB

    const int tid = threadIdx.x, wid = tid >> 5, lid = tid & 31;
    const int wrow = wid & 3, wcol = wid >> 2;
    const int i0 = ti * 64, j0 = tj * 64;

    // ---- precomputed loader offsets (combo/stage-invariant) ----
    uint32_t lo_sm[NLOAD];
    uint32_t lo_gl[NLOAD];
    #pragma unroll
    for (int p = 0; p < NLOAD; ++p) {
        const int v = p * 256 + tid;
        const int row = v / NCH, kcq = v % NCH;
        lo_sm[p] = (kcq >> 3) * 8192 + row * 128 +
                   (((kcq & 7) ^ (row & 7)) << 4);
        lo_gl[p] = row * C + kcq * 8;
    }

    const size_t HWC = (size_t)HW * C;
    auto load_stage = [&](int combo, int stage) {
        const __half* base = g_scratch + off + (size_t)combo * HWC;
        const __half* sA = base + (size_t)i0 * C;
        const __half* sB = base + (size_t)j0 * C;
        const uint32_t stb = sb + stage * STAGE_B;
        #pragma unroll
        for (int p = 0; p < NLOAD; ++p) {
            cp_async16(stb + lo_sm[p], sA + lo_gl[p]);
            cp_async16(stb + TILE_B + lo_sm[p], sB + lo_gl[p]);
        }
    };

    // ---- per-lane ldmatrix addressing (stage-invariant) ----
    const int mat = lid >> 3, lrow = lid & 7;
    const int a_row = wrow * 16 + ((mat & 1) << 3) + lrow;
    const int a_kh = mat >> 1;
    const int b_row0 = wcol * 32 + ((mat >> 1) << 3) + lrow;
    const int b_row1 = b_row0 + 16;
    const int b_kh = mat & 1;
    const uint32_t a_off  = a_row * 128;
    const uint32_t b_off0 = TILE_B + b_row0 * 128;
    const uint32_t b_off1 = TILE_B + b_row1 * 128;
    const int a_r7 = a_row & 7, b_r70 = b_row0 & 7, b_r71 = b_row1 & 7;

    // ---- preload NSTAGES-1 combos ----
    #pragma unroll
    for (int pc = 0; pc < NSTAGES - 1; ++pc) {
        load_stage(pc, pc); CP_COMMIT();
    }

    uint32_t acc[4][8];
    float wsum = 0.0f;
    const bool fullabove = (tj > ti);
    const int gi = lid >> 2, gj = (lid & 3) << 1;

    #pragma unroll 1
    for (int t = 0; t < 2; ++t) {
        #pragma unroll
        for (int b = 0; b < 4; ++b) {
            const int combo = t * 4 + b;
            if (NSTAGES >= 4) {
                if (combo <= 5)      { CP_WAIT(2); }
                else if (combo == 6) { CP_WAIT(1); }
                else                 { CP_WAIT(0); }
            } else {
                CP_WAIT(0);
            }
            __syncthreads();  // combo's stage ready; prior readers done
            if (combo + NSTAGES - 1 < 8) {
                load_stage(combo + NSTAGES - 1, (combo + NSTAGES - 1) % NSTAGES);
                CP_COMMIT();
            }

            const uint32_t stb = sb + (combo % NSTAGES) * STAGE_B;
            #pragma unroll
            for (int s = 0; s < 8; ++s) acc[b][s] = 0u;

            #pragma unroll
            for (int ks = 0; ks < KSTEPS; ++ks) {
                const int kb = ks >> 2, kc = (ks & 3) * 2;
                uint32_t af[4], b0[4], b1[4];
                ldmatrix_x4(af, stb + a_off  + kb * 8192 +
                                (((kc + a_kh) ^ a_r7)  << 4));
                ldmatrix_x4(b0, stb + b_off0 + kb * 8192 +
                                (((kc + b_kh) ^ b_r70) << 4));
                ldmatrix_x4(b1, stb + b_off1 + kb * 8192 +
                                (((kc + b_kh) ^ b_r71) << 4));
                mma_16816_h(acc[b] + 0, af, b0 + 0);   // h0 nb0 -> r0,r1
                mma_16816_h(acc[b] + 2, af, b0 + 2);   // h0 nb1 -> r2,r3
                mma_16816_h(acc[b] + 4, af, b1 + 0);   // h1 nb0 -> r4,r5
                mma_16816_h(acc[b] + 6, af, b1 + 2);   // h1 nb1 -> r6,r7
            }
        }

        // ---- per-phase f16x2 epilogue: base-2 softmax + |diff| ----
        #pragma unroll
        for (int r = 0; r < 8; ++r) {
            const __half2 A0 = u2h(acc[0][r]), A1 = u2h(acc[1][r]);
            const __half2 A2 = u2h(acc[2][r]), A3 = u2h(acc[3][r]);
            const __half2 m = __hmax2(__hmax2(A0, A1), __hmax2(A2, A3));
            const __half2 e0 = ex2_h2(__hsub2(A0, m));
            const __half2 e1 = ex2_h2(__hsub2(A1, m));
            const __half2 e2 = ex2_h2(__hsub2(A2, m));
            const __half2 e3 = ex2_h2(__hsub2(A3, m));
            const __half2 sum = __hadd2(__hadd2(e0, e1), __hadd2(e2, e3));
            const __half2 inv = rcp_h2(sum);
            const __half2 p0 = __hmul2(e0, inv), p1 = __hmul2(e1, inv);
            const __half2 p2 = __hmul2(e2, inv), p3 = __hmul2(e3, inv);

            if (t == 0) {
                aff[(0 * 8 + r) * 256 + tid] = h2u(p0);
                aff[(1 * 8 + r) * 256 + tid] = h2u(p1);
                aff[(2 * 8 + r) * 256 + tid] = h2u(p2);
                aff[(3 * 8 + r) * 256 + tid] = h2u(p3);
            } else {
                __half2 d = __habs2(__hsub2(u2h(aff[(0*8+r)*256 + tid]), p0));
                d = __hadd2(d, __habs2(__hsub2(u2h(aff[(1*8+r)*256 + tid]), p1)));
                d = __hadd2(d, __habs2(__hsub2(u2h(aff[(2*8+r)*256 + tid]), p2)));
                d = __hadd2(d, __habs2(__hsub2(u2h(aff[(3*8+r)*256 + tid]), p3)));
                const float2 dd = __half22float2(d);
                if (fullabove) {
                    wsum += dd.x + dd.y;
                } else {
                    const int mi = r >> 1;
                    const int i = i0 + wrow * 16 + gi + ((r & 1) << 3);
                    const int j = j0 + wcol * 32 + ((mi >> 1) << 4)
                                + ((mi & 1) << 3) + gj;
                    const float wlo = (j > i) ? 2.0f : ((j == i) ? 1.0f : 0.0f);
                    const float whi = (j + 1 > i) ? 2.0f : ((j + 1 == i) ? 1.0f : 0.0f);
                    wsum += wlo * dd.x + whi * dd.y;
                }
            }
        }
    }

    // ---- reduce: warp shfl -> smem -> single atomic ----
    if (fullabove) wsum *= 2.0f;
    #pragma unroll
    for (int s2 = 16; s2; s2 >>= 1) wsum += __shfl_xor_sync(0xFFFFFFFFu, wsum, s2);
    __syncthreads();
    float* wsums = (float*)smem;
    if (lid == 0) wsums[wid] = wsum;
    __syncthreads();
    if (tid == 0) {
        float tt = 0.0f;
        #pragma unroll
        for (int wq = 0; wq < 8; ++wq) tt += wsums[wq];
        atomicAdd(&g_sum[level], (double)tt);
    }
}

// Combined launch: first N_L1 blocks run the heavier C=128 tiles (scheduled
// early so the 2080 small C=64 blocks pack around them), rest run C=64.
// The last block to finish writes the final result (threadfence reduction).
#define N_L1 136
#define N_L0 2080
#define N_TOT (N_L0 + N_L1)

__global__ void __launch_bounds__(256, 2)
gram_fused(float* __restrict__ out)
{
    extern __shared__ char smem[];
    if (blockIdx.x < N_L1)
        gram_body<128, 2>(blockIdx.x, 1024, L1_OFF, 1, smem);
    else
        gram_body<64, 4>(blockIdx.x - N_L1, 4096, L0_OFF, 0, smem);

    // ---- last-block finalize (atomicInc wraps to 0 -> graph-replay safe) ----
    if (threadIdx.x == 0) {
        __threadfence();
        const unsigned old = atomicInc(&g_done, N_TOT - 1);
        if (old == N_TOT - 1) {
            const double n0 = 4.0 * 4096.0 * 4096.0;
            const double n1 = 4.0 * 1024.0 * 1024.0;
            out[0] = (float)((g_sum[0] / n0 + g_sum[1] / n1) * 0.5);
        }
    }
}

// ============================================================================
// Launch
// ============================================================================
extern "C" void kernel_launch(void* const* d_in, const int* in_sizes, int n_in,
                              void* d_out, int out_size)
{
    const float* fea1_0 = (const float*)d_in[0];  // (4, 64, 64, 64)
    const float* fea1_1 = (const float*)d_in[1];  // (4, 128, 32, 32)
    const float* fea2_0 = (const float*)d_in[2];
    const float* fea2_1 = (const float*)d_in[3];
    float* out = (float*)d_out;

    // smem: both bodies use exactly 96 KB -> 2 CTAs/SM
    const int smem_bytes = 98304;
    cudaFuncSetAttribute(gram_fused,
                         cudaFuncAttributeMaxDynamicSharedMemorySize, smem_bytes);

    convert_fused<<<dim3(80, 4, 2), 256>>>(fea1_0, fea2_0, fea1_1, fea2_1);

    gram_fused<<<N_TOT, 256, smem_bytes>>>(out);
}